// round 3
// baseline (speedup 1.0000x reference)
#include <cuda_runtime.h>
#include <math.h>

#define NQ      12
#define DIM     4096          // 2^12
#define NBATCH  4096
#define THREADS 512
#define AMPS    8             // DIM / THREADS amplitudes per thread

// Combined per-qubit gates: G_q = U3(layer1,q) @ U3(layer0,q)
// layout: [q][u00r,u00i,u01r,u01i,u10r,u10i,u11r,u11i]
__device__ float g_gates[NQ * 8];

struct C2 { float r, i; };
__device__ __forceinline__ C2 cmul(C2 a, C2 b) {
    C2 o; o.r = a.r * b.r - a.i * b.i; o.i = a.r * b.i + a.i * b.r; return o;
}
__device__ __forceinline__ C2 cadd(C2 a, C2 b) { C2 o; o.r = a.r + b.r; o.i = a.i + b.i; return o; }

// ---------------------------------------------------------------------------
// Prep: build 12 combined 2x2 gates from the per-layer U3 parameters.
// ---------------------------------------------------------------------------
__global__ void prep_gates_kernel(const float* __restrict__ thetas,
                                  const float* __restrict__ phis,
                                  const float* __restrict__ lams) {
    int q = threadIdx.x;
    if (q >= NQ) return;

    C2 U[2][4];  // U[layer][2x2 row-major]
    #pragma unroll
    for (int l = 0; l < 2; l++) {
        float th = thetas[l * NQ + q];
        float ph = phis[l * NQ + q];
        float la = lams[l * NQ + q];
        float s, c;
        sincosf(th * 0.5f, &s, &c);
        float sl, cl, sp, cp, spl, cpl;
        sincosf(la, &sl, &cl);
        sincosf(ph, &sp, &cp);
        sincosf(ph + la, &spl, &cpl);
        U[l][0] = (C2){c, 0.f};            // u00 = cos(th/2)
        U[l][1] = (C2){-cl * s, -sl * s};  // u01 = -e^{i lam} sin
        U[l][2] = (C2){cp * s, sp * s};    // u10 = e^{i phi} sin
        U[l][3] = (C2){cpl * c, spl * c};  // u11 = e^{i(phi+lam)} cos
    }
    // G = U[1] @ U[0]
    C2 G[4];
    G[0] = cadd(cmul(U[1][0], U[0][0]), cmul(U[1][1], U[0][2]));
    G[1] = cadd(cmul(U[1][0], U[0][1]), cmul(U[1][1], U[0][3]));
    G[2] = cadd(cmul(U[1][2], U[0][0]), cmul(U[1][3], U[0][2]));
    G[3] = cadd(cmul(U[1][2], U[0][1]), cmul(U[1][3], U[0][3]));

    float* g = &g_gates[q * 8];
    g[0] = G[0].r; g[1] = G[0].i;
    g[2] = G[1].r; g[3] = G[1].i;
    g[4] = G[2].r; g[5] = G[2].i;
    g[6] = G[3].r; g[7] = G[3].i;
}

// Complex 2x2 butterfly on a register pair, gate from shared memory.
__device__ __forceinline__ void bfly(float2& x0, float2& x1, const float* __restrict__ g) {
    const float u00r = g[0], u00i = g[1], u01r = g[2], u01i = g[3];
    const float u10r = g[4], u10i = g[5], u11r = g[6], u11i = g[7];
    float2 y0, y1;
    y0.x = u00r * x0.x - u00i * x0.y + u01r * x1.x - u01i * x1.y;
    y0.y = u00r * x0.y + u00i * x0.x + u01r * x1.y + u01i * x1.x;
    y1.x = u10r * x0.x - u10i * x0.y + u11r * x1.x - u11i * x1.y;
    y1.y = u10r * x0.y + u10i * x0.x + u11r * x1.y + u11i * x1.x;
    x0 = y0; x1 = y1;
}

// Ownership map for stage s (base bit b = 3s): thread t, local amp j holds
// global index ((t & ~m) << 3) | (j << b) | (t & m),  m = (1 << b) - 1.
__device__ __forceinline__ int idx_stage(int s, int t, int j) {
    switch (s) {
        case 0: return (t << 3) | j;
        case 1: return ((t >> 3) << 6) | (j << 3) | (t & 7);
        case 2: return ((t >> 6) << 9) | (j << 6) | (t & 63);
        default: return (j << 9) | t;
    }
}

// Apply the 3 butterfly bits of stage s (global bits b, b+1, b+2) on the
// 8 register amplitudes. Bit beta maps to qubit (11 - beta) in kron order.
__device__ __forceinline__ void stage_regs(float2 a[AMPS], int b, const float* __restrict__ sg) {
    {   // local bit 0: pairs (0,1)(2,3)(4,5)(6,7)
        const float* g = &sg[(NQ - 1 - (b + 0)) * 8];
        bfly(a[0], a[1], g); bfly(a[2], a[3], g);
        bfly(a[4], a[5], g); bfly(a[6], a[7], g);
    }
    {   // local bit 1: pairs (0,2)(1,3)(4,6)(5,7)
        const float* g = &sg[(NQ - 1 - (b + 1)) * 8];
        bfly(a[0], a[2], g); bfly(a[1], a[3], g);
        bfly(a[4], a[6], g); bfly(a[5], a[7], g);
    }
    {   // local bit 2: pairs (0,4)(1,5)(2,6)(3,7)
        const float* g = &sg[(NQ - 1 - (b + 2)) * 8];
        bfly(a[0], a[4], g); bfly(a[1], a[5], g);
        bfly(a[2], a[6], g); bfly(a[3], a[7], g);
    }
}

// ---------------------------------------------------------------------------
// Main: one CTA per batch row. 8 amps per thread in registers; 4 register
// stages of 3 butterfly bits each; 3 smem exchanges between stages.
// ---------------------------------------------------------------------------
__global__ __launch_bounds__(THREADS, 2)
void qc_kernel(const float* __restrict__ in, float* __restrict__ out) {
    __shared__ float2 st[DIM];            // 32 KB exchange buffer
    __shared__ float sg[NQ * 8];
    __shared__ float swarp[THREADS / 32];
    __shared__ float sinv;

    const int t = threadIdx.x;
    const size_t row = (size_t)blockIdx.x * DIM;

    if (t < NQ * 8) sg[t] = g_gates[t];

    // Load 8 consecutive floats (stage-0 ownership: i = t*8 + j), real state.
    float2 a[AMPS];
    const float4* xin = (const float4*)(in + row);
    float4 v0 = xin[t * 2];
    float4 v1 = xin[t * 2 + 1];
    a[0] = make_float2(v0.x, 0.f); a[1] = make_float2(v0.y, 0.f);
    a[2] = make_float2(v0.z, 0.f); a[3] = make_float2(v0.w, 0.f);
    a[4] = make_float2(v1.x, 0.f); a[5] = make_float2(v1.y, 0.f);
    a[6] = make_float2(v1.z, 0.f); a[7] = make_float2(v1.w, 0.f);

    // ||x||^2 block reduction (probabilities scale by 1/||x||^2 by linearity)
    float acc = v0.x * v0.x + v0.y * v0.y + v0.z * v0.z + v0.w * v0.w
              + v1.x * v1.x + v1.y * v1.y + v1.z * v1.z + v1.w * v1.w;
    #pragma unroll
    for (int o = 16; o > 0; o >>= 1) acc += __shfl_xor_sync(0xFFFFFFFFu, acc, o);
    if ((t & 31) == 0) swarp[t >> 5] = acc;
    __syncthreads();                      // also publishes sg
    if (t == 0) {
        float s = 0.f;
        #pragma unroll
        for (int w = 0; w < THREADS / 32; w++) s += swarp[w];
        sinv = 1.f / s;
    }

    // Stage 0: bits 0..2 (zero imaginary parts fold away in the first bit)
    stage_regs(a, 0, sg);

    // Exchanges + stages 1..3
    #pragma unroll
    for (int s = 0; s < 3; s++) {
        #pragma unroll
        for (int j = 0; j < AMPS; j++) st[idx_stage(s, t, j)] = a[j];
        __syncthreads();
        #pragma unroll
        for (int j = 0; j < AMPS; j++) a[j] = st[idx_stage(s + 1, t, j)];
        __syncthreads();                  // protect st before next stage's writes
        stage_regs(a, 3 * (s + 1), sg);
    }

    // Epilogue: probabilities. Stage-3 ownership: i = (j<<9) | t  -> coalesced.
    const float inv = sinv;               // written before first sync, stable since
    float* o = out + row;
    #pragma unroll
    for (int j = 0; j < AMPS; j++) {
        float2 v = a[j];
        o[(j << 9) | t] = (v.x * v.x + v.y * v.y) * inv;
    }
}

extern "C" void kernel_launch(void* const* d_in, const int* in_sizes, int n_in,
                              void* d_out, int out_size) {
    const float* inputs = (const float*)d_in[0];   // [4096, 4096]
    const float* thetas = (const float*)d_in[1];   // [2, 12]
    const float* phis   = (const float*)d_in[2];   // [2, 12]
    const float* lams   = (const float*)d_in[3];   // [2, 12]
    float* out = (float*)d_out;

    prep_gates_kernel<<<1, 32>>>(thetas, phis, lams);
    qc_kernel<<<NBATCH, THREADS>>>(inputs, out);
}

// round 5
// speedup vs baseline: 1.1128x; 1.1128x over previous
#include <cuda_runtime.h>
#include <math.h>

#define NQ      12
#define DIM     4096          // 2^12
#define NBATCH  4096
#define THREADS 512
#define AMPS    8             // DIM / THREADS amplitudes per thread

typedef unsigned long long ull;

// Packed combined gates: G_q = U3(layer1,q) @ U3(layer0,q), stored as 8
// f32x2 constants per qubit:
//   k=0:(u00r,u00r) 1:(-u00i,u00i) 2:(u01r,u01r) 3:(-u01i,u01i)
//   k=4:(u10r,u10r) 5:(-u10i,u10i) 6:(u11r,u11r) 7:(-u11i,u11i)
// Amp convention: low lane = re, high lane = im.
__device__ ull g_gates2[NQ * 8];

struct C2 { float r, i; };
__device__ __forceinline__ C2 cmul(C2 a, C2 b) {
    C2 o; o.r = a.r * b.r - a.i * b.i; o.i = a.r * b.i + a.i * b.r; return o;
}
__device__ __forceinline__ C2 cadd(C2 a, C2 b) { C2 o; o.r = a.r + b.r; o.i = a.i + b.i; return o; }

__device__ __forceinline__ ull pack2(float lo, float hi) {
    return (ull)__float_as_uint(lo) | ((ull)__float_as_uint(hi) << 32);
}

// ---------------------------------------------------------------------------
// Prep: build 12 combined 2x2 gates, packed for f32x2 butterflies.
// ---------------------------------------------------------------------------
__global__ void prep_gates_kernel(const float* __restrict__ thetas,
                                  const float* __restrict__ phis,
                                  const float* __restrict__ lams) {
    int q = threadIdx.x;
    if (q >= NQ) return;

    C2 U[2][4];
    #pragma unroll
    for (int l = 0; l < 2; l++) {
        float th = thetas[l * NQ + q];
        float ph = phis[l * NQ + q];
        float la = lams[l * NQ + q];
        float s, c;
        sincosf(th * 0.5f, &s, &c);
        float sl, cl, sp, cp, spl, cpl;
        sincosf(la, &sl, &cl);
        sincosf(ph, &sp, &cp);
        sincosf(ph + la, &spl, &cpl);
        U[l][0] = (C2){c, 0.f};
        U[l][1] = (C2){-cl * s, -sl * s};
        U[l][2] = (C2){cp * s, sp * s};
        U[l][3] = (C2){cpl * c, spl * c};
    }
    C2 G[4];
    G[0] = cadd(cmul(U[1][0], U[0][0]), cmul(U[1][1], U[0][2]));
    G[1] = cadd(cmul(U[1][0], U[0][1]), cmul(U[1][1], U[0][3]));
    G[2] = cadd(cmul(U[1][2], U[0][0]), cmul(U[1][3], U[0][2]));
    G[3] = cadd(cmul(U[1][2], U[0][1]), cmul(U[1][3], U[0][3]));

    ull* g = &g_gates2[q * 8];
    #pragma unroll
    for (int e = 0; e < 4; e++) {
        g[e * 2 + 0] = pack2(G[e].r, G[e].r);
        g[e * 2 + 1] = pack2(-G[e].i, G[e].i);
    }
}

// ---------------------------------------------------------------------------
// Packed f32x2 helpers
// ---------------------------------------------------------------------------
__device__ __forceinline__ ull f2mul(ull a, ull b) {
    ull d; asm("mul.rn.f32x2 %0, %1, %2;" : "=l"(d) : "l"(a), "l"(b)); return d;
}
__device__ __forceinline__ ull f2fma(ull a, ull b, ull c) {
    ull d; asm("fma.rn.f32x2 %0, %1, %2, %3;" : "=l"(d) : "l"(a), "l"(b), "l"(c)); return d;
}
__device__ __forceinline__ ull swap64(ull x) {   // (re,im) -> (im,re)
    return (x >> 32) | (x << 32);
}

struct GateP { ull g00r, g00i, g01r, g01i, g10r, g10i, g11r, g11i; };

__device__ __forceinline__ GateP load_gate(const ull* __restrict__ sg, int bit) {
    const ull* p = sg + (NQ - 1 - bit) * 8;   // bit beta <-> qubit (11-beta)
    GateP g;
    g.g00r = p[0]; g.g00i = p[1]; g.g01r = p[2]; g.g01i = p[3];
    g.g10r = p[4]; g.g10i = p[5]; g.g11r = p[6]; g.g11i = p[7];
    return g;
}

// Complex 2x2 butterfly, both amplitudes packed f32x2.
// y0 = u00*x0 + u01*x1 ; y1 = u10*x0 + u11*x1
__device__ __forceinline__ void bfly2(ull& x0, ull& x1, const GateP& g) {
    ull q0 = swap64(x0);
    ull q1 = swap64(x1);
    ull y0 = f2mul(g.g00r, x0);
    y0 = f2fma(g.g00i, q0, y0);
    y0 = f2fma(g.g01r, x1, y0);
    y0 = f2fma(g.g01i, q1, y0);
    ull y1 = f2mul(g.g10r, x0);
    y1 = f2fma(g.g10i, q0, y1);
    y1 = f2fma(g.g11r, x1, y1);
    y1 = f2fma(g.g11i, q1, y1);
    x0 = y0; x1 = y1;
}

// Ownership map for stage s (base bit b = 3s): thread t, local amp j holds
// global index ((t & ~m) << 3) | (j << b) | (t & m),  m = (1 << b) - 1.
__device__ __forceinline__ int idx_stage(int s, int t, int j) {
    switch (s) {
        case 0: return (t << 3) | j;
        case 1: return ((t >> 3) << 6) | (j << 3) | (t & 7);
        case 2: return ((t >> 6) << 9) | (j << 6) | (t & 63);
        default: return (j << 9) | t;
    }
}

// Bank-conflict-free XOR swizzle for the 64-bit exchange buffer.
// Hand-verified: for all six (stage, read/write) patterns, each 16-lane
// phase maps to 16 distinct 8-byte bank pairs (swz(i)&15 injective per phase).
__device__ __forceinline__ int swz(int i) {
    return i ^ ((i >> 4) & 7) ^ ((i >> 3) & 8);
}

// Apply the 3 butterfly bits of a stage (global bits b, b+1, b+2).
__device__ __forceinline__ void stage_regs(ull a[AMPS], int b, const ull* __restrict__ sg) {
    {
        GateP g = load_gate(sg, b + 0);
        bfly2(a[0], a[1], g); bfly2(a[2], a[3], g);
        bfly2(a[4], a[5], g); bfly2(a[6], a[7], g);
    }
    {
        GateP g = load_gate(sg, b + 1);
        bfly2(a[0], a[2], g); bfly2(a[1], a[3], g);
        bfly2(a[4], a[6], g); bfly2(a[5], a[7], g);
    }
    {
        GateP g = load_gate(sg, b + 2);
        bfly2(a[0], a[4], g); bfly2(a[1], a[5], g);
        bfly2(a[2], a[6], g); bfly2(a[3], a[7], g);
    }
}

// ---------------------------------------------------------------------------
// Main: one CTA per batch row. 8 packed amps per thread; 4 register stages
// of 3 bits each; 3 conflict-free smem exchanges.
// ---------------------------------------------------------------------------
__global__ __launch_bounds__(THREADS, 2)
void qc_kernel(const float* __restrict__ in, float* __restrict__ out) {
    __shared__ ull st[DIM];               // 32 KB exchange buffer (swizzled)
    __shared__ ull sgp[NQ * 8];           // packed gate table, 768 B
    __shared__ float swarp[THREADS / 32];
    __shared__ float sinv;

    const int t = threadIdx.x;
    const size_t row = (size_t)blockIdx.x * DIM;

    if (t < NQ * 8) sgp[t] = g_gates2[t];

    // Load 8 consecutive floats (stage-0 ownership i = t*8 + j), imag = 0.
    ull a[AMPS];
    const float4* xin = (const float4*)(in + row);
    float4 v0 = xin[t * 2];
    float4 v1 = xin[t * 2 + 1];
    a[0] = (ull)__float_as_uint(v0.x); a[1] = (ull)__float_as_uint(v0.y);
    a[2] = (ull)__float_as_uint(v0.z); a[3] = (ull)__float_as_uint(v0.w);
    a[4] = (ull)__float_as_uint(v1.x); a[5] = (ull)__float_as_uint(v1.y);
    a[6] = (ull)__float_as_uint(v1.z); a[7] = (ull)__float_as_uint(v1.w);

    // ||x||^2 reduction (probabilities scale by 1/||x||^2 by linearity)
    float acc = v0.x * v0.x + v0.y * v0.y + v0.z * v0.z + v0.w * v0.w
              + v1.x * v1.x + v1.y * v1.y + v1.z * v1.z + v1.w * v1.w;
    #pragma unroll
    for (int o = 16; o > 0; o >>= 1) acc += __shfl_xor_sync(0xFFFFFFFFu, acc, o);
    if ((t & 31) == 0) swarp[t >> 5] = acc;
    __syncthreads();                      // also publishes sgp
    if (t == 0) {
        float s = 0.f;
        #pragma unroll
        for (int w = 0; w < THREADS / 32; w++) s += swarp[w];
        sinv = 1.f / s;
    }

    // Stage 0: bits 0..2
    stage_regs(a, 0, sgp);

    // Exchanges + stages 1..3
    #pragma unroll
    for (int s = 0; s < 3; s++) {
        #pragma unroll
        for (int j = 0; j < AMPS; j++) st[swz(idx_stage(s, t, j))] = a[j];
        __syncthreads();
        #pragma unroll
        for (int j = 0; j < AMPS; j++) a[j] = st[swz(idx_stage(s + 1, t, j))];
        __syncthreads();                  // protect st before next stage's writes
        stage_regs(a, 3 * (s + 1), sgp);
    }

    // Epilogue. Stage-3 ownership i = (j<<9)|t -> fully coalesced STG.32.
    const float inv = sinv;
    float* o = out + row;
    #pragma unroll
    for (int j = 0; j < AMPS; j++) {
        float re = __uint_as_float((unsigned)(a[j] & 0xFFFFFFFFu));
        float im = __uint_as_float((unsigned)(a[j] >> 32));
        o[(j << 9) | t] = (re * re + im * im) * inv;
    }
}

extern "C" void kernel_launch(void* const* d_in, const int* in_sizes, int n_in,
                              void* d_out, int out_size) {
    const float* inputs = (const float*)d_in[0];   // [4096, 4096]
    const float* thetas = (const float*)d_in[1];   // [2, 12]
    const float* phis   = (const float*)d_in[2];   // [2, 12]
    const float* lams   = (const float*)d_in[3];   // [2, 12]
    float* out = (float*)d_out;

    prep_gates_kernel<<<1, 32>>>(thetas, phis, lams);
    qc_kernel<<<NBATCH, THREADS>>>(inputs, out);
}

// round 7
// speedup vs baseline: 1.3863x; 1.2458x over previous
#include <cuda_runtime.h>
#include <math.h>

#define NQ      12
#define DIM     4096          // 2^12
#define NBATCH  4096
#define THREADS 256
#define AMPS    16            // DIM / THREADS amplitudes per thread

typedef unsigned long long ull;

// Packed combined gates: G_q = U3(layer1,q) @ U3(layer0,q), stored as 8
// f32x2 constants per qubit:
//   k=0:(u00r,u00r) 1:(-u00i,u00i) 2:(u01r,u01r) 3:(-u01i,u01i)
//   k=4:(u10r,u10r) 5:(-u10i,u10i) 6:(u11r,u11r) 7:(-u11i,u11i)
// Amp convention: low lane = re, high lane = im.
// Entries [NQ*8 .. NQ*8+3]: column-packed gate for qubit 11 (global bit 0),
// used for the real-input first butterfly: c00=(u00r,u00i) c01 c10 c11.
__device__ ull g_gates2[NQ * 8 + 4];

struct C2 { float r, i; };
__device__ __forceinline__ C2 cmul(C2 a, C2 b) {
    C2 o; o.r = a.r * b.r - a.i * b.i; o.i = a.r * b.i + a.i * b.r; return o;
}
__device__ __forceinline__ C2 cadd(C2 a, C2 b) { C2 o; o.r = a.r + b.r; o.i = a.i + b.i; return o; }

__device__ __forceinline__ ull pack2(float lo, float hi) {
    return (ull)__float_as_uint(lo) | ((ull)__float_as_uint(hi) << 32);
}

// ---------------------------------------------------------------------------
// Prep: build 12 combined 2x2 gates, packed for f32x2 butterflies.
// ---------------------------------------------------------------------------
__global__ void prep_gates_kernel(const float* __restrict__ thetas,
                                  const float* __restrict__ phis,
                                  const float* __restrict__ lams) {
    int q = threadIdx.x;
    if (q >= NQ) return;

    C2 U[2][4];
    #pragma unroll
    for (int l = 0; l < 2; l++) {
        float th = thetas[l * NQ + q];
        float ph = phis[l * NQ + q];
        float la = lams[l * NQ + q];
        float s, c;
        sincosf(th * 0.5f, &s, &c);
        float sl, cl, sp, cp, spl, cpl;
        sincosf(la, &sl, &cl);
        sincosf(ph, &sp, &cp);
        sincosf(ph + la, &spl, &cpl);
        U[l][0] = (C2){c, 0.f};
        U[l][1] = (C2){-cl * s, -sl * s};
        U[l][2] = (C2){cp * s, sp * s};
        U[l][3] = (C2){cpl * c, spl * c};
    }
    C2 G[4];
    G[0] = cadd(cmul(U[1][0], U[0][0]), cmul(U[1][1], U[0][2]));
    G[1] = cadd(cmul(U[1][0], U[0][1]), cmul(U[1][1], U[0][3]));
    G[2] = cadd(cmul(U[1][2], U[0][0]), cmul(U[1][3], U[0][2]));
    G[3] = cadd(cmul(U[1][2], U[0][1]), cmul(U[1][3], U[0][3]));

    ull* g = &g_gates2[q * 8];
    #pragma unroll
    for (int e = 0; e < 4; e++) {
        g[e * 2 + 0] = pack2(G[e].r, G[e].r);
        g[e * 2 + 1] = pack2(-G[e].i, G[e].i);
    }
    if (q == NQ - 1) {   // column-packed copy for the real-input first bit
        g_gates2[NQ * 8 + 0] = pack2(G[0].r, G[0].i);  // c00
        g_gates2[NQ * 8 + 1] = pack2(G[1].r, G[1].i);  // c01
        g_gates2[NQ * 8 + 2] = pack2(G[2].r, G[2].i);  // c10
        g_gates2[NQ * 8 + 3] = pack2(G[3].r, G[3].i);  // c11
    }
}

// ---------------------------------------------------------------------------
// Packed f32x2 helpers
// ---------------------------------------------------------------------------
__device__ __forceinline__ ull f2mul(ull a, ull b) {
    ull d; asm("mul.rn.f32x2 %0, %1, %2;" : "=l"(d) : "l"(a), "l"(b)); return d;
}
__device__ __forceinline__ ull f2fma(ull a, ull b, ull c) {
    ull d; asm("fma.rn.f32x2 %0, %1, %2, %3;" : "=l"(d) : "l"(a), "l"(b), "l"(c)); return d;
}
__device__ __forceinline__ ull swap64(ull x) {   // (re,im) -> (im,re)
    return (x >> 32) | (x << 32);
}
__device__ __forceinline__ ull splat2(float x) { return pack2(x, x); }

struct GateP { ull g00r, g00i, g01r, g01i, g10r, g10i, g11r, g11i; };

// 4x LDS.128 gate load.
__device__ __forceinline__ GateP load_gate(const ull* __restrict__ sg, int bit) {
    const ulonglong2* p = (const ulonglong2*)(sg + (NQ - 1 - bit) * 8);  // bit beta <-> qubit 11-beta
    ulonglong2 a = p[0], b = p[1], c = p[2], d = p[3];
    GateP g;
    g.g00r = a.x; g.g00i = a.y; g.g01r = b.x; g.g01i = b.y;
    g.g10r = c.x; g.g10i = c.y; g.g11r = d.x; g.g11i = d.y;
    return g;
}

// Complex 2x2 butterfly, both amplitudes packed f32x2 (re in lane0, im in lane1).
__device__ __forceinline__ void bfly2(ull& x0, ull& x1, const GateP& g) {
    ull q0 = swap64(x0);
    ull q1 = swap64(x1);
    ull y0 = f2mul(g.g00r, x0);
    y0 = f2fma(g.g00i, q0, y0);
    y0 = f2fma(g.g01r, x1, y0);
    y0 = f2fma(g.g01i, q1, y0);
    ull y1 = f2mul(g.g10r, x0);
    y1 = f2fma(g.g10i, q0, y1);
    y1 = f2fma(g.g11r, x1, y1);
    y1 = f2fma(g.g11i, q1, y1);
    x0 = y0; x1 = y1;
}

// Apply one butterfly bit (local bit l) across 16 register amplitudes.
__device__ __forceinline__ void apply_bit(ull a[AMPS], int l, const GateP& g) {
    #pragma unroll
    for (int j = 0; j < AMPS; j++) {
        if (((j >> l) & 1) == 0) bfly2(a[j], a[j | (1 << l)], g);
    }
}

// Ownership map for stage s (base bit b = 4s): thread t, local amp j holds
// global index ((t & ~m) << 4) | (j << b) | (t & m),  m = (1 << b) - 1.
__device__ __forceinline__ int idx_stage(int s, int t, int j) {
    switch (s) {
        case 0: return (t << 4) | j;
        case 1: return ((t >> 4) << 8) | (j << 4) | (t & 15);
        default: return (j << 8) | t;
    }
}

// Bank-conflict-free XOR swizzle (involution) for the 64-bit exchange buffer.
// For all four (stage, rd/wr) patterns, swz(i)&15 is injective over each
// 16-lane phase: stage0 j^lane, stage1 lane^j, stage2 lane^const.
__device__ __forceinline__ int swz(int i) {
    return i ^ ((i >> 4) & 15);
}

// ---------------------------------------------------------------------------
// Main: one CTA per batch row. 16 packed amps per thread; 3 register stages
// of 4 bits each; 2 conflict-free smem exchanges.
// ---------------------------------------------------------------------------
__global__ __launch_bounds__(THREADS, 3)
void qc_kernel(const float* __restrict__ in, float* __restrict__ out) {
    __shared__ ull st[DIM];                       // 32 KB exchange buffer (swizzled)
    __shared__ __align__(16) ull sgp[NQ * 8 + 4]; // packed gate table
    __shared__ float swarp[THREADS / 32];
    __shared__ float sinv;

    const int t = threadIdx.x;
    const size_t row = (size_t)blockIdx.x * DIM;

    if (t < NQ * 8 + 4) sgp[t] = g_gates2[t];

    // Load 16 consecutive floats (stage-0 ownership i = t*16 + j).
    float x[AMPS];
    const float4* xin = (const float4*)(in + row);
    float acc = 0.f;
    #pragma unroll
    for (int k = 0; k < 4; k++) {
        float4 v = xin[t * 4 + k];
        x[k * 4 + 0] = v.x; x[k * 4 + 1] = v.y;
        x[k * 4 + 2] = v.z; x[k * 4 + 3] = v.w;
        acc += v.x * v.x + v.y * v.y + v.z * v.z + v.w * v.w;
    }

    // ||x||^2 reduction (probabilities scale by 1/||x||^2 by linearity)
    #pragma unroll
    for (int o = 16; o > 0; o >>= 1) acc += __shfl_xor_sync(0xFFFFFFFFu, acc, o);
    if ((t & 31) == 0) swarp[t >> 5] = acc;
    __syncthreads();                      // also publishes sgp
    if (t == 0) {
        float s = 0.f;
        #pragma unroll
        for (int w = 0; w < THREADS / 32; w++) s += swarp[w];
        sinv = 1.f / s;
    }

    // ---- Stage 0: bits 0..3 ----
    ull a[AMPS];
    {   // bit 0 on REAL inputs, column-packed gates: y = c0*(x0,x0) + c1*(x1,x1)
        const ulonglong2* cp = (const ulonglong2*)(sgp + NQ * 8);
        ulonglong2 cA = cp[0], cB = cp[1];    // c00,c01 / c10,c11
        #pragma unroll
        for (int j = 0; j < AMPS; j += 2) {
            ull s0 = splat2(x[j]);
            ull s1 = splat2(x[j + 1]);
            a[j]     = f2fma(cA.y, s1, f2mul(cA.x, s0));
            a[j + 1] = f2fma(cB.y, s1, f2mul(cB.x, s0));
        }
    }
    { GateP g = load_gate(sgp, 1); apply_bit(a, 1, g); }
    { GateP g = load_gate(sgp, 2); apply_bit(a, 2, g); }
    { GateP g = load_gate(sgp, 3); apply_bit(a, 3, g); }

    // ---- Exchanges + stages 1..2 ----
    #pragma unroll
    for (int s = 0; s < 2; s++) {
        #pragma unroll
        for (int j = 0; j < AMPS; j++) st[swz(idx_stage(s, t, j))] = a[j];
        __syncthreads();
        #pragma unroll
        for (int j = 0; j < AMPS; j++) a[j] = st[swz(idx_stage(s + 1, t, j))];
        __syncthreads();                  // protect st before next stage's writes
        const int b = 4 * (s + 1);
        { GateP g = load_gate(sgp, b + 0); apply_bit(a, 0, g); }
        { GateP g = load_gate(sgp, b + 1); apply_bit(a, 1, g); }
        { GateP g = load_gate(sgp, b + 2); apply_bit(a, 2, g); }
        { GateP g = load_gate(sgp, b + 3); apply_bit(a, 3, g); }
    }

    // Epilogue. Stage-2 ownership i = (j<<8)|t -> fully coalesced STG.32.
    const float inv = sinv;
    float* o = out + row;
    #pragma unroll
    for (int j = 0; j < AMPS; j++) {
        float re = __uint_as_float((unsigned)(a[j] & 0xFFFFFFFFu));
        float im = __uint_as_float((unsigned)(a[j] >> 32));
        o[(j << 8) | t] = (re * re + im * im) * inv;
    }
}

extern "C" void kernel_launch(void* const* d_in, const int* in_sizes, int n_in,
                              void* d_out, int out_size) {
    const float* inputs = (const float*)d_in[0];   // [4096, 4096]
    const float* thetas = (const float*)d_in[1];   // [2, 12]
    const float* phis   = (const float*)d_in[2];   // [2, 12]
    const float* lams   = (const float*)d_in[3];   // [2, 12]
    float* out = (float*)d_out;

    prep_gates_kernel<<<1, 32>>>(thetas, phis, lams);
    qc_kernel<<<NBATCH, THREADS>>>(inputs, out);
}